// round 1
// baseline (speedup 1.0000x reference)
#include <cuda_runtime.h>
#include <math.h>

#define NB 1024
#define EPSV 1e-8f

// Per-box precomputed data (80 B)
struct BP {
    float cx, cy, rad, area;    // center, circumradius(+margin), dx*dy
    float cr, sr, hdx, hdy;     // cos/sin of ry, half extents
    float zlo, zhi, vol, pad;   // z range, volume
    float corx[4];              // rotated corner x
    float cory[4];              // rotated corner y
};

__device__ BP g_gtp[NB];
__device__ BP g_prp[NB];
__device__ int g_order[NB];
__device__ unsigned g_mask[NB * 32];
__device__ int g_keepflag[NB];
__device__ int g_kept[NB];
__device__ int g_kcount;

__device__ __forceinline__ void fill_bp(BP& p, const float* b) {
    float x = b[0], y = b[1], z = b[2];
    float dx = b[3], dy = b[4], dz = b[5], r = b[6];
    float cr = cosf(r), sr = sinf(r);
    p.cx = x; p.cy = y; p.cr = cr; p.sr = sr;
    p.hdx = 0.5f * dx; p.hdy = 0.5f * dy;
    p.rad = sqrtf(p.hdx * p.hdx + p.hdy * p.hdy) + 1e-3f;
    p.area = dx * dy;
    p.vol = dx * dy * dz;
    p.zlo = z - 0.5f * dz; p.zhi = z + 0.5f * dz;
    const float sx[4] = {0.5f, 0.5f, -0.5f, -0.5f};
    const float sy[4] = {0.5f, -0.5f, -0.5f, 0.5f};
#pragma unroll
    for (int c = 0; c < 4; c++) {
        float lx = sx[c] * dx, ly = sy[c] * dy;
        p.corx[c] = lx * cr - ly * sr + x;
        p.cory[c] = lx * sr + ly * cr + y;
    }
}

// Exact replication of reference _rect_inter_area (same collection order,
// same tolerances, stable angle sort, shoelace).
__device__ float inter_area(const BP& A, const BP& B) {
    float px[24], py[24];
    int m = 0;
    // corners of A in B
#pragma unroll
    for (int c = 0; c < 4; c++) {
        float dx = A.corx[c] - B.cx, dy = A.cory[c] - B.cy;
        float lx = dx * B.cr + dy * B.sr;
        float ly = -dx * B.sr + dy * B.cr;
        if (fabsf(lx) <= B.hdx + 1e-5f && fabsf(ly) <= B.hdy + 1e-5f) {
            px[m] = A.corx[c]; py[m] = A.cory[c]; m++;
        }
    }
    // corners of B in A
#pragma unroll
    for (int c = 0; c < 4; c++) {
        float dx = B.corx[c] - A.cx, dy = B.cory[c] - A.cy;
        float lx = dx * A.cr + dy * A.sr;
        float ly = -dx * A.sr + dy * A.cr;
        if (fabsf(lx) <= A.hdx + 1e-5f && fabsf(ly) <= A.hdy + 1e-5f) {
            px[m] = B.corx[c]; py[m] = B.cory[c]; m++;
        }
    }
    // edge intersections (A edge i outer, B edge j inner: row-major like reference)
#pragma unroll
    for (int i = 0; i < 4; i++) {
        int i1 = (i + 1) & 3;
        float a0x = A.corx[i], a0y = A.cory[i];
        float d1x = A.corx[i1] - a0x, d1y = A.cory[i1] - a0y;
#pragma unroll
        for (int j = 0; j < 4; j++) {
            int j1 = (j + 1) & 3;
            float b0x = B.corx[j], b0y = B.cory[j];
            float d2x = B.corx[j1] - b0x, d2y = B.cory[j1] - b0y;
            float r0x = b0x - a0x, r0y = b0y - a0y;
            float den = d1x * d2y - d1y * d2x;
            if (fabsf(den) > EPSV) {
                float t = (r0x * d2y - r0y * d2x) / den;
                float u = (r0x * d1y - r0y * d1x) / den;
                if (t >= 0.f && t <= 1.f && u >= 0.f && u <= 1.f) {
                    px[m] = a0x + t * d1x; py[m] = a0y + t * d1y; m++;
                }
            }
        }
    }
    if (m < 3) return 0.0f;
    float sx = 0.f, sy = 0.f;
    for (int i = 0; i < m; i++) { sx += px[i]; sy += py[i]; }
    float inv = 1.0f / (float)m;
    float ctx = sx * inv, cty = sy * inv;
    float ang[24];
    for (int i = 0; i < m; i++) {
        px[i] -= ctx; py[i] -= cty;
        ang[i] = atan2f(py[i], px[i]);
    }
    // stable insertion sort by angle
    for (int i = 1; i < m; i++) {
        float a = ang[i], x = px[i], y = py[i];
        int j = i - 1;
        while (j >= 0 && ang[j] > a) {
            ang[j + 1] = ang[j]; px[j + 1] = px[j]; py[j + 1] = py[j];
            j--;
        }
        ang[j + 1] = a; px[j + 1] = x; py[j + 1] = y;
    }
    float s = 0.f;
    for (int i = 0; i < m; i++) {
        int k2 = (i + 1 < m) ? i + 1 : 0;
        s += px[i] * py[k2] - py[i] * px[k2];
    }
    return 0.5f * fabsf(s);
}

__device__ __forceinline__ float iou_bev(const BP& A, const BP& B) {
    float dx = A.cx - B.cx, dy = A.cy - B.cy;
    float rs = A.rad + B.rad;
    if (dx * dx + dy * dy > rs * rs) return 0.0f;
    float inter = inter_area(A, B);
    return inter / fmaxf(A.area + B.area - inter, EPSV);
}

// Prep boxes + trivial outputs (reg_valid, label copy)
__global__ void k_prep(const float* __restrict__ labels,
                       const float* __restrict__ pred,
                       const float* __restrict__ gt,
                       const float* __restrict__ cls,
                       float* __restrict__ out) {
    int t = blockIdx.x * blockDim.x + threadIdx.x;
    if (t < NB) {
        fill_bp(g_prp[t], pred + t * 7);
        float s = 1.0f / (1.0f + expf(-cls[t]));
        float lb = labels[t];
        out[t] = (s > 0.55f && lb > 0.55f) ? 1.0f : 0.0f;
        out[NB + t] = lb;
    } else if (t < 2 * NB) {
        int i = t - NB;
        fill_bp(g_gtp[i], gt + i * 8);
    }
}

// O(N^2) exact rank = stable argsort(-scores)
__global__ void k_rank(const float* __restrict__ sc) {
    int i = blockIdx.x * blockDim.x + threadIdx.x;
    if (i >= NB) return;
    float si = sc[i];
    int r = 0;
    for (int j = 0; j < NB; j++) {
        float sj = sc[j];
        r += (sj > si) || (sj == si && j < i);
    }
    g_order[r] = i;
}

// Pairwise suppression bitmask in sorted space (only j > i bits set)
__global__ void k_nmsmask() {
    int i = blockIdx.x;
    int oi = g_order[i];
    BP A = g_gtp[oi];
    for (int j = threadIdx.x; j < NB; j += blockDim.x) {
        bool f = false;
        if (j > i) {
            int oj = g_order[j];
            f = iou_bev(A, g_gtp[oj]) > 0.1f;
        }
        unsigned bal = __ballot_sync(0xffffffffu, f);
        if ((threadIdx.x & 31) == 0) g_mask[i * 32 + (j >> 5)] = bal;
    }
}

// Serial greedy NMS on warp 0; keep bits in registers (word per lane)
__global__ void k_nms() {
    __shared__ unsigned skeep[32];
    if (threadIdx.x < 32) {
        int lane = threadIdx.x;
        unsigned keepw = 0xFFFFFFFFu;
#pragma unroll 8
        for (int i = 0; i < NB; i++) {
            unsigned mrow = g_mask[i * 32 + lane];   // unconditional: pipelines
            unsigned w = __shfl_sync(0xffffffffu, keepw, i >> 5);
            bool c = (w >> (i & 31)) & 1u;
            keepw &= c ? ~mrow : 0xFFFFFFFFu;
        }
        skeep[lane] = keepw;
    }
    __syncthreads();
    for (int j = threadIdx.x; j < NB; j += blockDim.x) {
        g_keepflag[g_order[j]] = (skeep[j >> 5] >> (j & 31)) & 1u;
    }
}

// Compact kept gt indices in ascending original order (block scan)
__global__ void k_compact() {
    __shared__ int sf[NB];
    int t = threadIdx.x;
    int f = g_keepflag[t];
    sf[t] = f;
    __syncthreads();
    for (int off = 1; off < NB; off <<= 1) {
        int v = sf[t];
        int add = (t >= off) ? sf[t - off] : 0;
        __syncthreads();
        sf[t] = v + add;
        __syncthreads();
    }
    if (f) g_kept[sf[t] - 1] = t;
    if (t == NB - 1) g_kcount = sf[t];
}

// Per-pred-row iou3d over kept gt; max/argmax with jnp.argmax tie semantics
__global__ void k_row(float* __restrict__ out) {
    int i = blockIdx.x;
    BP A = g_prp[i];
    int kc = g_kcount;
    float bv = 0.0f;
    int bi = 0;
    for (int k = threadIdx.x; k < kc; k += blockDim.x) {
        int j = g_kept[k];
        const BP& B = g_gtp[j];
        float dx = A.cx - B.cx, dy = A.cy - B.cy;
        float rs = A.rad + B.rad;
        float v = 0.0f;
        if (dx * dx + dy * dy <= rs * rs) {
            float inter = inter_area(A, B);
            float oh = fmaxf(fminf(A.zhi, B.zhi) - fmaxf(A.zlo, B.zlo), 0.0f);
            float i3 = inter * oh;
            v = i3 / fmaxf(A.vol + B.vol - i3, EPSV);
        }
        if (v > bv || (v == bv && v > 0.0f && j < bi)) { bv = v; bi = j; }
    }
    __shared__ float sv[128];
    __shared__ int si[128];
    sv[threadIdx.x] = bv;
    si[threadIdx.x] = bi;
    __syncthreads();
    for (int s = 64; s > 0; s >>= 1) {
        if (threadIdx.x < s) {
            float ov = sv[threadIdx.x + s];
            int oi = si[threadIdx.x + s];
            if (ov > sv[threadIdx.x] ||
                (ov == sv[threadIdx.x] && oi < si[threadIdx.x])) {
                sv[threadIdx.x] = ov; si[threadIdx.x] = oi;
            }
        }
        __syncthreads();
    }
    if (threadIdx.x == 0) {
        float mo = sv[0];
        mo = (mo > 0.75f) ? 1.0f : ((mo < 0.25f) ? 0.0f : mo);
        out[2 * NB + i] = mo;
        out[3 * NB + i] = (float)si[0];
    }
}

extern "C" void kernel_launch(void* const* d_in, const int* in_sizes, int n_in,
                              void* d_out, int out_size) {
    const float* labels = (const float*)d_in[0];   // rcnn_cls_labels (N)
    const float* pred   = (const float*)d_in[1];   // pred_boxes (N,7)
    const float* gt     = (const float*)d_in[2];   // gt_boxes (N,8)
    const float* cls    = (const float*)d_in[3];   // rcnn_cls (N)
    float* out = (float*)d_out;                    // [reg_valid|labels|max_ov|assign]

    k_prep<<<(2 * NB + 127) / 128, 128>>>(labels, pred, gt, cls, out);
    k_rank<<<(NB + 127) / 128, 128>>>(labels);
    k_nmsmask<<<NB, 128>>>();
    k_nms<<<1, 256>>>();
    k_compact<<<1, NB>>>();
    k_row<<<NB, 128>>>(out);
}

// round 2
// speedup vs baseline: 1.8235x; 1.8235x over previous
#include <cuda_runtime.h>
#include <math.h>

#define NB 1024
#define EPSV 1e-8f

// Per-box precomputed data
struct BP {
    float cx, cy, rad, area;
    float cr, sr, hdx, hdy;
    float zlo, zhi, vol, pad;
    float corx[4];
    float cory[4];
};

__device__ BP g_gtp[NB];
__device__ BP g_prp[NB];
__device__ int g_order[NB];
__device__ unsigned g_mask[NB * 32];
__device__ int g_kept[NB];
__device__ int g_kcount;

__device__ __forceinline__ void fill_bp(BP& p, const float* b) {
    float x = b[0], y = b[1], z = b[2];
    float dx = b[3], dy = b[4], dz = b[5], r = b[6];
    float cr = cosf(r), sr = sinf(r);
    p.cx = x; p.cy = y; p.cr = cr; p.sr = sr;
    p.hdx = 0.5f * dx; p.hdy = 0.5f * dy;
    p.rad = sqrtf(p.hdx * p.hdx + p.hdy * p.hdy) + 1e-3f;
    p.area = dx * dy;
    p.vol = dx * dy * dz;
    p.zlo = z - 0.5f * dz; p.zhi = z + 0.5f * dz;
    const float sx[4] = {0.5f, 0.5f, -0.5f, -0.5f};
    const float sy[4] = {0.5f, -0.5f, -0.5f, 0.5f};
#pragma unroll
    for (int c = 0; c < 4; c++) {
        float lx = sx[c] * dx, ly = sy[c] * dy;
        p.corx[c] = lx * cr - ly * sr + x;
        p.cory[c] = lx * sr + ly * cr + y;
    }
}

// Exact replication of reference _rect_inter_area
__device__ float inter_area(const BP& A, const BP& B) {
    float px[24], py[24];
    int m = 0;
#pragma unroll
    for (int c = 0; c < 4; c++) {
        float dx = A.corx[c] - B.cx, dy = A.cory[c] - B.cy;
        float lx = dx * B.cr + dy * B.sr;
        float ly = -dx * B.sr + dy * B.cr;
        if (fabsf(lx) <= B.hdx + 1e-5f && fabsf(ly) <= B.hdy + 1e-5f) {
            px[m] = A.corx[c]; py[m] = A.cory[c]; m++;
        }
    }
#pragma unroll
    for (int c = 0; c < 4; c++) {
        float dx = B.corx[c] - A.cx, dy = B.cory[c] - A.cy;
        float lx = dx * A.cr + dy * A.sr;
        float ly = -dx * A.sr + dy * A.cr;
        if (fabsf(lx) <= A.hdx + 1e-5f && fabsf(ly) <= A.hdy + 1e-5f) {
            px[m] = B.corx[c]; py[m] = B.cory[c]; m++;
        }
    }
#pragma unroll
    for (int i = 0; i < 4; i++) {
        int i1 = (i + 1) & 3;
        float a0x = A.corx[i], a0y = A.cory[i];
        float d1x = A.corx[i1] - a0x, d1y = A.cory[i1] - a0y;
#pragma unroll
        for (int j = 0; j < 4; j++) {
            int j1 = (j + 1) & 3;
            float b0x = B.corx[j], b0y = B.cory[j];
            float d2x = B.corx[j1] - b0x, d2y = B.cory[j1] - b0y;
            float r0x = b0x - a0x, r0y = b0y - a0y;
            float den = d1x * d2y - d1y * d2x;
            if (fabsf(den) > EPSV) {
                float t = (r0x * d2y - r0y * d2x) / den;
                float u = (r0x * d1y - r0y * d1x) / den;
                if (t >= 0.f && t <= 1.f && u >= 0.f && u <= 1.f) {
                    px[m] = a0x + t * d1x; py[m] = a0y + t * d1y; m++;
                }
            }
        }
    }
    if (m < 3) return 0.0f;
    float sx = 0.f, sy = 0.f;
    for (int i = 0; i < m; i++) { sx += px[i]; sy += py[i]; }
    float inv = 1.0f / (float)m;
    float ctx = sx * inv, cty = sy * inv;
    float ang[24];
    for (int i = 0; i < m; i++) {
        px[i] -= ctx; py[i] -= cty;
        ang[i] = atan2f(py[i], px[i]);
    }
    for (int i = 1; i < m; i++) {
        float a = ang[i], x = px[i], y = py[i];
        int j = i - 1;
        while (j >= 0 && ang[j] > a) {
            ang[j + 1] = ang[j]; px[j + 1] = px[j]; py[j + 1] = py[j];
            j--;
        }
        ang[j + 1] = a; px[j + 1] = x; py[j + 1] = y;
    }
    float s = 0.f;
    for (int i = 0; i < m; i++) {
        int k2 = (i + 1 < m) ? i + 1 : 0;
        s += px[i] * py[k2] - py[i] * px[k2];
    }
    return 0.5f * fabsf(s);
}

__device__ __forceinline__ float iou_bev(const BP& A, const BP& B) {
    float dx = A.cx - B.cx, dy = A.cy - B.cy;
    float rs = A.rad + B.rad;
    if (dx * dx + dy * dy > rs * rs) return 0.0f;
    float inter = inter_area(A, B);
    return inter / fmaxf(A.area + B.area - inter, EPSV);
}

// Fused: prep boxes + trivial outputs (blocks 0..15), rank (blocks 16..23)
__global__ void k_prep(const float* __restrict__ labels,
                       const float* __restrict__ pred,
                       const float* __restrict__ gt,
                       const float* __restrict__ cls,
                       float* __restrict__ out) {
    int b = blockIdx.x;
    if (b < 16) {
        int t = b * 128 + threadIdx.x;
        if (t < NB) {
            fill_bp(g_prp[t], pred + t * 7);
            float s = 1.0f / (1.0f + expf(-cls[t]));
            float lb = labels[t];
            out[t] = (s > 0.55f && lb > 0.55f) ? 1.0f : 0.0f;
            out[NB + t] = lb;
        } else {
            int i = t - NB;
            fill_bp(g_gtp[i], gt + i * 8);
        }
    } else {
        // rank: stable argsort(-labels); block handles 128 i's
        __shared__ float ssc[NB];
        for (int j = threadIdx.x; j < NB; j += 128) ssc[j] = labels[j];
        __syncthreads();
        int i = (b - 16) * 128 + threadIdx.x;
        float si = ssc[i];
        int r = 0;
#pragma unroll 8
        for (int j = 0; j < NB; j++) {
            float sj = ssc[j];
            r += (sj > si) || (sj == si && j < i);
        }
        g_order[r] = i;
    }
}

// Pairwise suppression bitmask in sorted space (only j > i bits set)
__global__ void k_nmsmask() {
    int i = blockIdx.x;
    int oi = g_order[i];
    BP A = g_gtp[oi];
    for (int j = threadIdx.x; j < NB; j += blockDim.x) {
        bool f = false;
        if (j > i) {
            int oj = g_order[j];
            f = iou_bev(A, g_gtp[oj]) > 0.1f;
        }
        unsigned bal = __ballot_sync(0xffffffffu, f);
        if ((threadIdx.x & 31) == 0) g_mask[i * 32 + (j >> 5)] = bal;
    }
}

// Blocked serial NMS on warp 0 (register bit-matrix, double-buffered loads),
// then compact kept original indices with ballot scan. 256 threads.
__global__ void k_nms() {
    __shared__ unsigned skeep[32];      // keep bits, sorted space
    __shared__ unsigned char sflag[NB]; // keep flag in original-index order
    __shared__ int swt[8];              // warp totals for compact scan
    int tid = threadIdx.x;

    if (tid < 32) {
        const int lane = tid;
        unsigned keepw = 0xFFFFFFFFu;   // lane owns sorted word `lane`
        unsigned cur[32], nxt[32];
#pragma unroll
        for (int i = 0; i < 32; i++) cur[i] = g_mask[i * 32 + lane];
        for (int b = 0; b < 32; b++) {
            // prefetch next block's 32x32 sub-matrix (hidden behind resolve)
            if (b + 1 < 32) {
#pragma unroll
                for (int i = 0; i < 32; i++)
                    nxt[i] = g_mask[((b + 1) * 32 + i) * 32 + lane];
            }
            unsigned K = __shfl_sync(0xffffffffu, keepw, b);
            // serial resolve: lane b's cur[] is the intra column (word b of
            // each row in this block). All lanes compute redundantly; only
            // lane b's K is meaningful. Rows only have bits j>i, so bit i is
            // final by step i.
#pragma unroll
            for (int i = 0; i < 32; i++) {
                unsigned bc = (unsigned)(((int)(K << (31 - i))) >> 31);
                K &= ~(cur[i] & bc);
            }
            unsigned kf = __shfl_sync(0xffffffffu, K, b);
            // parallel apply: OR of rows of final-kept candidates
            unsigned sup = 0;
#pragma unroll
            for (int i = 0; i < 32; i++) {
                unsigned bc = (unsigned)(((int)(kf << (31 - i))) >> 31);
                sup |= cur[i] & bc;
            }
            keepw &= ~sup;
#pragma unroll
            for (int i = 0; i < 32; i++) cur[i] = nxt[i];
        }
        skeep[lane] = keepw;
    }
    __syncthreads();
    // scatter keep flags to original-index order
#pragma unroll
    for (int q = 0; q < 4; q++) {
        int j = tid * 4 + q;
        int o = g_order[j];
        sflag[o] = (skeep[j >> 5] >> (j & 31)) & 1u;
    }
    __syncthreads();
    // compact: thread t owns original indices 4t..4t+3
    int f0 = sflag[tid * 4 + 0], f1 = sflag[tid * 4 + 1];
    int f2 = sflag[tid * 4 + 2], f3 = sflag[tid * 4 + 3];
    int cnt = f0 + f1 + f2 + f3;
    int lane = tid & 31, wid = tid >> 5;
    int pre = cnt;
#pragma unroll
    for (int s = 1; s < 32; s <<= 1) {
        int v = __shfl_up_sync(0xffffffffu, pre, s);
        if (lane >= s) pre += v;
    }
    int wtot = __shfl_sync(0xffffffffu, pre, 31);
    if (lane == 31) swt[wid] = pre;   // inclusive warp total
    (void)wtot;
    __syncthreads();
    int base = 0;
    for (int w = 0; w < 8; w++) base += (w < wid) ? swt[w] : 0;
    int pos = base + pre - cnt;       // exclusive prefix
    if (f0) g_kept[pos++] = tid * 4 + 0;
    if (f1) g_kept[pos++] = tid * 4 + 1;
    if (f2) g_kept[pos++] = tid * 4 + 2;
    if (f3) g_kept[pos]   = tid * 4 + 3;
    if (tid == 255) g_kcount = base + pre;
}

// Per-pred-row iou3d over kept gt; max/argmax with jnp.argmax tie semantics
__global__ void k_row(float* __restrict__ out) {
    int i = blockIdx.x;
    BP A = g_prp[i];
    int kc = g_kcount;
    float bv = 0.0f;
    int bi = 0;
    for (int k = threadIdx.x; k < kc; k += blockDim.x) {
        int j = g_kept[k];
        const BP& B = g_gtp[j];
        float dx = A.cx - B.cx, dy = A.cy - B.cy;
        float rs = A.rad + B.rad;
        float v = 0.0f;
        if (dx * dx + dy * dy <= rs * rs) {
            float inter = inter_area(A, B);
            float oh = fmaxf(fminf(A.zhi, B.zhi) - fmaxf(A.zlo, B.zlo), 0.0f);
            float i3 = inter * oh;
            v = i3 / fmaxf(A.vol + B.vol - i3, EPSV);
        }
        if (v > bv || (v == bv && v > 0.0f && j < bi)) { bv = v; bi = j; }
    }
    __shared__ float sv[128];
    __shared__ int si[128];
    sv[threadIdx.x] = bv;
    si[threadIdx.x] = bi;
    __syncthreads();
    for (int s = 64; s > 0; s >>= 1) {
        if (threadIdx.x < s) {
            float ov = sv[threadIdx.x + s];
            int oi = si[threadIdx.x + s];
            if (ov > sv[threadIdx.x] ||
                (ov == sv[threadIdx.x] && oi < si[threadIdx.x])) {
                sv[threadIdx.x] = ov; si[threadIdx.x] = oi;
            }
        }
        __syncthreads();
    }
    if (threadIdx.x == 0) {
        float mo = sv[0];
        mo = (mo > 0.75f) ? 1.0f : ((mo < 0.25f) ? 0.0f : mo);
        out[2 * NB + i] = mo;
        out[3 * NB + i] = (float)si[0];
    }
}

extern "C" void kernel_launch(void* const* d_in, const int* in_sizes, int n_in,
                              void* d_out, int out_size) {
    const float* labels = (const float*)d_in[0];
    const float* pred   = (const float*)d_in[1];
    const float* gt     = (const float*)d_in[2];
    const float* cls    = (const float*)d_in[3];
    float* out = (float*)d_out;

    k_prep<<<24, 128>>>(labels, pred, gt, cls, out);
    k_nmsmask<<<NB, 128>>>();
    k_nms<<<1, 256>>>();
    k_row<<<NB, 128>>>(out);
}

// round 3
// speedup vs baseline: 2.2921x; 1.2570x over previous
#include <cuda_runtime.h>
#include <math.h>

#define NB 1024
#define EPSV 1e-8f
#define QC2 4096   // nms pair queue per block
#define QC4 4096   // row pair queue per block
#define RPB 16     // rows per block in k_row

struct BP {
    float cx, cy, rad, area;
    float cr, sr, hdx, hdy;
    float zlo, zhi, vol, pad;
    float corx[4];
    float cory[4];
};

__device__ BP g_gtp[NB];
__device__ BP g_prp[NB];
__device__ float4 g_gtc[NB];     // gt (cx,cy,rad,-)
__device__ float4 g_prc[NB];     // pred (cx,cy,rad,-)
__device__ int g_order[NB];
__device__ unsigned g_mask[NB * 32];
__device__ float4 g_keptc[NB];   // kept (cx,cy,rad, idx-as-bits)
__device__ int g_kcount;

__device__ __forceinline__ void fill_bp(BP& p, const float* b, float4* cen) {
    float x = b[0], y = b[1], z = b[2];
    float dx = b[3], dy = b[4], dz = b[5], r = b[6];
    float cr = cosf(r), sr = sinf(r);
    p.cx = x; p.cy = y; p.cr = cr; p.sr = sr;
    p.hdx = 0.5f * dx; p.hdy = 0.5f * dy;
    float rad = sqrtf(p.hdx * p.hdx + p.hdy * p.hdy) + 1e-3f;
    p.rad = rad;
    p.area = dx * dy;
    p.vol = dx * dy * dz;
    p.zlo = z - 0.5f * dz; p.zhi = z + 0.5f * dz;
    const float sx[4] = {0.5f, 0.5f, -0.5f, -0.5f};
    const float sy[4] = {0.5f, -0.5f, -0.5f, 0.5f};
#pragma unroll
    for (int c = 0; c < 4; c++) {
        float lx = sx[c] * dx, ly = sy[c] * dy;
        p.corx[c] = lx * cr - ly * sr + x;
        p.cory[c] = lx * sr + ly * cr + y;
    }
    *cen = make_float4(x, y, rad, 0.0f);
}

// Exact replication of reference _rect_inter_area
__device__ float inter_area(const BP& A, const BP& B) {
    float px[24], py[24];
    int m = 0;
#pragma unroll
    for (int c = 0; c < 4; c++) {
        float dx = A.corx[c] - B.cx, dy = A.cory[c] - B.cy;
        float lx = dx * B.cr + dy * B.sr;
        float ly = -dx * B.sr + dy * B.cr;
        if (fabsf(lx) <= B.hdx + 1e-5f && fabsf(ly) <= B.hdy + 1e-5f) {
            px[m] = A.corx[c]; py[m] = A.cory[c]; m++;
        }
    }
#pragma unroll
    for (int c = 0; c < 4; c++) {
        float dx = B.corx[c] - A.cx, dy = B.cory[c] - A.cy;
        float lx = dx * A.cr + dy * A.sr;
        float ly = -dx * A.sr + dy * A.cr;
        if (fabsf(lx) <= A.hdx + 1e-5f && fabsf(ly) <= A.hdy + 1e-5f) {
            px[m] = B.corx[c]; py[m] = B.cory[c]; m++;
        }
    }
#pragma unroll
    for (int i = 0; i < 4; i++) {
        int i1 = (i + 1) & 3;
        float a0x = A.corx[i], a0y = A.cory[i];
        float d1x = A.corx[i1] - a0x, d1y = A.cory[i1] - a0y;
#pragma unroll
        for (int j = 0; j < 4; j++) {
            int j1 = (j + 1) & 3;
            float b0x = B.corx[j], b0y = B.cory[j];
            float d2x = B.corx[j1] - b0x, d2y = B.cory[j1] - b0y;
            float r0x = b0x - a0x, r0y = b0y - a0y;
            float den = d1x * d2y - d1y * d2x;
            if (fabsf(den) > EPSV) {
                float t = (r0x * d2y - r0y * d2x) / den;
                float u = (r0x * d1y - r0y * d1x) / den;
                if (t >= 0.f && t <= 1.f && u >= 0.f && u <= 1.f) {
                    px[m] = a0x + t * d1x; py[m] = a0y + t * d1y; m++;
                }
            }
        }
    }
    if (m < 3) return 0.0f;
    float sx = 0.f, sy = 0.f;
    for (int i = 0; i < m; i++) { sx += px[i]; sy += py[i]; }
    float inv = 1.0f / (float)m;
    float ctx = sx * inv, cty = sy * inv;
    float ang[24];
    for (int i = 0; i < m; i++) {
        px[i] -= ctx; py[i] -= cty;
        ang[i] = atan2f(py[i], px[i]);
    }
    for (int i = 1; i < m; i++) {
        float a = ang[i], x = px[i], y = py[i];
        int j = i - 1;
        while (j >= 0 && ang[j] > a) {
            ang[j + 1] = ang[j]; px[j + 1] = px[j]; py[j + 1] = py[j];
            j--;
        }
        ang[j + 1] = a; px[j + 1] = x; py[j + 1] = y;
    }
    float s = 0.f;
    for (int i = 0; i < m; i++) {
        int k2 = (i + 1 < m) ? i + 1 : 0;
        s += px[i] * py[k2] - py[i] * px[k2];
    }
    return 0.5f * fabsf(s);
}

// ---------- k1: prep + rank + pos + mask zero ----------
__global__ void k_prep(const float* __restrict__ labels,
                       const float* __restrict__ pred,
                       const float* __restrict__ gt,
                       const float* __restrict__ cls,
                       float* __restrict__ out) {
    int b = blockIdx.x;
    if (b < 8) {
        // rank: stable argsort(-labels)
        __shared__ float ssc[NB];
        for (int j = threadIdx.x; j < NB; j += 128) ssc[j] = labels[j];
        __syncthreads();
        int i = b * 128 + threadIdx.x;
        float si = ssc[i];
        int r = 0;
#pragma unroll 8
        for (int j = 0; j < NB; j++) {
            float sj = ssc[j];
            r += (sj > si) || (sj == si && j < i);
        }
        g_order[r] = i;
    } else if (b < 24) {
        int t = (b - 8) * 128 + threadIdx.x;
        if (t < NB) {
            fill_bp(g_prp[t], pred + t * 7, &g_prc[t]);
            float s = 1.0f / (1.0f + expf(-cls[t]));
            float lb = labels[t];
            out[t] = (s > 0.55f && lb > 0.55f) ? 1.0f : 0.0f;
            out[NB + t] = lb;
        } else {
            int i = t - NB;
            fill_bp(g_gtp[i], gt + i * 8, &g_gtc[i]);
        }
    } else {
        // zero the suppression mask (32768 words / 8 blocks)
        int base = (b - 24) * 4096 + threadIdx.x;
        for (int w = 0; w < 32; w++) g_mask[base + w * 128] = 0u;
    }
}

// ---------- k2: NMS heavy pairs: gen (circ) -> smem queue -> compute ----------
__device__ __forceinline__ void nms_pair(int i, int j, const int* sidx) {
    const BP& A = g_gtp[sidx[i]];
    const BP& B = g_gtp[sidx[j]];
    float inter = inter_area(A, B);
    float v = inter / fmaxf(A.area + B.area - inter, EPSV);
    if (v > 0.1f) atomicOr(&g_mask[i * 32 + (j >> 5)], 1u << (j & 31));
}

__global__ void k_nmspairs() {
    __shared__ float4 sc[NB];
    __shared__ int sidx[NB];
    __shared__ unsigned q[QC2];
    __shared__ int qn;
    int tid = threadIdx.x;
    for (int i = tid; i < NB; i += 256) {
        int o = g_order[i];
        sidx[i] = o;
        sc[i] = g_gtc[o];
    }
    if (tid == 0) qn = 0;
    __syncthreads();
    for (int i = blockIdx.x; i < NB - 1; i += gridDim.x) {
        float4 a = sc[i];
        for (int j = i + 1 + tid; j < NB; j += 256) {
            float4 bb = sc[j];
            float dx = a.x - bb.x, dy = a.y - bb.y;
            float rs = a.z + bb.z;
            if (dx * dx + dy * dy <= rs * rs) {
                int p = atomicAdd(&qn, 1);
                unsigned e = ((unsigned)i << 10) | (unsigned)j;
                if (p < QC2) q[p] = e;
                else nms_pair(i, j, sidx);   // overflow fallback (never expected)
            }
        }
    }
    __syncthreads();
    int n = min(qn, QC2);
    for (int t = tid; t < n; t += 256) {
        unsigned e = q[t];
        nms_pair((int)(e >> 10), (int)(e & 1023u), sidx);
    }
}

// ---------- k3: serial greedy resolve + compact kept ----------
__global__ void k_nms() {
    __shared__ unsigned skeep[32];
    __shared__ unsigned char sflag[NB];
    __shared__ int swt[8];
    int tid = threadIdx.x;

    if (tid < 32) {
        const int lane = tid;
        unsigned keepw = 0xFFFFFFFFu;
        unsigned cur[32], nxt[32];
#pragma unroll
        for (int i = 0; i < 32; i++) cur[i] = g_mask[i * 32 + lane];
        for (int b = 0; b < 32; b++) {
            if (b + 1 < 32) {
#pragma unroll
                for (int i = 0; i < 32; i++)
                    nxt[i] = g_mask[((b + 1) * 32 + i) * 32 + lane];
            }
            // any bits at all in this block's rows (this lane's column)?
            unsigned orall = 0;
#pragma unroll
            for (int i = 0; i < 32; i++) orall |= cur[i];
            unsigned bal = __ballot_sync(0xffffffffu, orall != 0u);
            if (bal != 0u) {
                unsigned K = __shfl_sync(0xffffffffu, keepw, b);
                if ((bal >> b) & 1u) {
                    // serial resolve on diag sub-block (lane b's data; all
                    // lanes compute redundantly, lane b's result used)
#pragma unroll
                    for (int i = 0; i < 32; i++) {
                        unsigned bc = (unsigned)(((int)(K << (31 - i))) >> 31);
                        K &= ~(cur[i] & bc);
                    }
                }
                unsigned kf = __shfl_sync(0xffffffffu, K, b);
                unsigned sup = 0;
#pragma unroll
                for (int i = 0; i < 32; i++) {
                    unsigned bc = (unsigned)(((int)(kf << (31 - i))) >> 31);
                    sup |= cur[i] & bc;
                }
                keepw &= ~sup;
            }
#pragma unroll
            for (int i = 0; i < 32; i++) cur[i] = nxt[i];
        }
        skeep[lane] = keepw;
    }
    __syncthreads();
#pragma unroll
    for (int qq = 0; qq < 4; qq++) {
        int j = tid * 4 + qq;
        int o = g_order[j];
        sflag[o] = (skeep[j >> 5] >> (j & 31)) & 1u;
    }
    __syncthreads();
    int f0 = sflag[tid * 4 + 0], f1 = sflag[tid * 4 + 1];
    int f2 = sflag[tid * 4 + 2], f3 = sflag[tid * 4 + 3];
    int cnt = f0 + f1 + f2 + f3;
    int lane = tid & 31, wid = tid >> 5;
    int pre = cnt;
#pragma unroll
    for (int s = 1; s < 32; s <<= 1) {
        int v = __shfl_up_sync(0xffffffffu, pre, s);
        if (lane >= s) pre += v;
    }
    if (lane == 31) swt[wid] = pre;
    __syncthreads();
    int base = 0;
    for (int w = 0; w < 8; w++) base += (w < wid) ? swt[w] : 0;
    int pos = base + pre - cnt;
    if (f0) { int ix = tid*4+0; float4 c = g_gtc[ix]; c.w = __int_as_float(ix); g_keptc[pos++] = c; }
    if (f1) { int ix = tid*4+1; float4 c = g_gtc[ix]; c.w = __int_as_float(ix); g_keptc[pos++] = c; }
    if (f2) { int ix = tid*4+2; float4 c = g_gtc[ix]; c.w = __int_as_float(ix); g_keptc[pos++] = c; }
    if (f3) { int ix = tid*4+3; float4 c = g_gtc[ix]; c.w = __int_as_float(ix); g_keptc[pos]   = c; }
    if (tid == 255) g_kcount = base + pre;
}

// ---------- k4: row heavy pairs: gen -> smem queue -> compute -> per-row max ----------
__device__ __forceinline__ void row_pair(int row0, unsigned e,
                                         unsigned long long* best) {
    int rl = (int)(e >> 10);
    int j = (int)(e & 1023u);
    const BP& A = g_prp[row0 + rl];
    const BP& B = g_gtp[j];
    float inter = inter_area(A, B);
    float oh = fmaxf(fminf(A.zhi, B.zhi) - fmaxf(A.zlo, B.zlo), 0.0f);
    float i3 = inter * oh;
    float v = i3 / fmaxf(A.vol + B.vol - i3, EPSV);
    unsigned long long key =
        ((unsigned long long)__float_as_uint(v) << 32) |
        (unsigned long long)(0xFFFFFFFFu - (unsigned)j);
    atomicMax(&best[rl], key);
}

__global__ void k_row(float* __restrict__ out) {
    __shared__ float4 skept[NB];
    __shared__ unsigned q[QC4];
    __shared__ unsigned long long best[RPB];
    __shared__ int qn;
    int tid = threadIdx.x;
    int K = g_kcount;
    for (int i = tid; i < K; i += 256) skept[i] = g_keptc[i];
    if (tid < RPB) best[tid] = 0xFFFFFFFFull;  // v=0, j=0
    if (tid == 0) qn = 0;
    __syncthreads();
    int row0 = blockIdx.x * RPB;
#pragma unroll
    for (int rl = 0; rl < RPB; rl++) {
        float4 a = g_prc[row0 + rl];
        for (int k = tid; k < K; k += 256) {
            float4 bb = skept[k];
            float dx = a.x - bb.x, dy = a.y - bb.y;
            float rs = a.z + bb.z;
            if (dx * dx + dy * dy <= rs * rs) {
                unsigned e = ((unsigned)rl << 10) |
                             (unsigned)__float_as_int(bb.w);
                int p = atomicAdd(&qn, 1);
                if (p < QC4) q[p] = e;
                else row_pair(row0, e, best);
            }
        }
    }
    __syncthreads();
    int n = min(qn, QC4);
    for (int t = tid; t < n; t += 256) row_pair(row0, q[t], best);
    __syncthreads();
    if (tid < RPB) {
        unsigned long long key = best[tid];
        float mo = __uint_as_float((unsigned)(key >> 32));
        int j = (int)(0xFFFFFFFFu - (unsigned)(key & 0xFFFFFFFFull));
        mo = (mo > 0.75f) ? 1.0f : ((mo < 0.25f) ? 0.0f : mo);
        out[2 * NB + row0 + tid] = mo;
        out[3 * NB + row0 + tid] = (float)j;
    }
}

extern "C" void kernel_launch(void* const* d_in, const int* in_sizes, int n_in,
                              void* d_out, int out_size) {
    const float* labels = (const float*)d_in[0];
    const float* pred   = (const float*)d_in[1];
    const float* gt     = (const float*)d_in[2];
    const float* cls    = (const float*)d_in[3];
    float* out = (float*)d_out;

    k_prep<<<32, 128>>>(labels, pred, gt, cls, out);
    k_nmspairs<<<128, 256>>>();
    k_nms<<<1, 256>>>();
    k_row<<<64, 256>>>(out);
}